// round 5
// baseline (speedup 1.0000x reference)
#include <cuda_runtime.h>
#include <cuda_bf16.h>

// relu(sum(relu(x))) over N = 2^25 fp32. HBM-bound streaming reduction.
// Unroll-2 grid-stride (MLP=2/warp, ~22 regs) + single full wave
// (148*8 CTAs @ 8 CTAs/SM) + fused last-block-done tail reduce.

#define NTHREADS 256
#define NBLOCKS (148 * 8)   // 1184: one full wave at 8 CTAs/SM

__device__ float g_partials[NBLOCKS];
__device__ unsigned int g_count = 0;

__device__ __forceinline__ float relu4(float4 v)
{
    return fmaxf(v.x, 0.0f) + fmaxf(v.y, 0.0f)
         + fmaxf(v.z, 0.0f) + fmaxf(v.w, 0.0f);
}

__device__ __forceinline__ float block_reduce(float acc, float* warp_sums)
{
    #pragma unroll
    for (int off = 16; off > 0; off >>= 1)
        acc += __shfl_xor_sync(0xFFFFFFFFu, acc, off);

    int lane = threadIdx.x & 31;
    int wid = threadIdx.x >> 5;
    if (lane == 0) warp_sums[wid] = acc;
    __syncthreads();

    float s = 0.0f;
    if (wid == 0) {
        s = (lane < NTHREADS / 32) ? warp_sums[lane] : 0.0f;
        #pragma unroll
        for (int off = 16; off > 0; off >>= 1)
            s += __shfl_xor_sync(0xFFFFFFFFu, s, off);
    }
    return s;  // valid in warp 0 lane 0
}

__global__ void __launch_bounds__(NTHREADS, 8) kan_fused_kernel(
    const float* __restrict__ x, int n_vec4, float* __restrict__ out)
{
    const float4* __restrict__ xv = reinterpret_cast<const float4*>(x);
    int tid = blockIdx.x * blockDim.x + threadIdx.x;
    const int stride = NBLOCKS * NTHREADS;

    // Unroll x2: two independent LDG.128 in flight, two accumulators.
    float a0 = 0.0f, a1 = 0.0f;
    int i = tid;
    for (; i + stride < n_vec4; i += 2 * stride) {
        float4 v0 = xv[i];
        float4 v1 = xv[i + stride];
        a0 += relu4(v0);
        a1 += relu4(v1);
    }
    if (i < n_vec4)
        a0 += relu4(xv[i]);

    float acc = a0 + a1;

    __shared__ float warp_sums[NTHREADS / 32];
    float bsum = block_reduce(acc, warp_sums);

    // Publish partial, elect last block.
    __shared__ bool is_last;
    if (threadIdx.x == 0) {
        g_partials[blockIdx.x] = bsum;
        __threadfence();
        unsigned int prev = atomicAdd(&g_count, 1u);
        is_last = (prev == (unsigned int)(gridDim.x - 1));
    }
    __syncthreads();

    if (is_last) {
        // 256 threads reduce NBLOCKS partials in fixed order.
        float facc = 0.0f;
        for (int k = threadIdx.x; k < NBLOCKS; k += NTHREADS)
            facc += g_partials[k];

        __syncthreads();  // warp_sums reuse
        float total = block_reduce(facc, warp_sums);

        if (threadIdx.x == 0) {
            out[0] = fmaxf(total, 0.0f);  // outer relu
            g_count = 0;                  // reset for graph replay
        }
    }
}

extern "C" void kernel_launch(void* const* d_in, const int* in_sizes, int n_in,
                              void* d_out, int out_size)
{
    const float* x = (const float*)d_in[0];
    float* out = (float*)d_out;
    int n = in_sizes[0];
    int n_vec4 = n / 4;  // N = 2^25, divisible by 4

    kan_fused_kernel<<<NBLOCKS, NTHREADS>>>(x, n_vec4, out);
}

// round 6
// speedup vs baseline: 1.0012x; 1.0012x over previous
#include <cuda_runtime.h>
#include <cuda_bf16.h>

// relu(sum(relu(x))) over N = 2^25 fp32. HBM-bound streaming reduction.
// sm_103a 256-bit loads (ld.global.nc.v8.f32 -> LDG.E.256): half the LDG
// count / L1tex queue entries per byte vs float4. Unroll-2, two accumulator
// chains, single full wave (148*8 CTAs @ 8/SM), fused last-block tail.

#define NTHREADS 256
#define NBLOCKS (148 * 8)   // 1184: one full wave at 8 CTAs/SM

__device__ float g_partials[NBLOCKS];
__device__ unsigned int g_count = 0;

// 256-bit read-only global load (sm_100+).
__device__ __forceinline__ void ldg256(const float* __restrict__ p,
                                       float4& a, float4& b)
{
    asm volatile("ld.global.nc.v8.f32 {%0,%1,%2,%3,%4,%5,%6,%7}, [%8];"
                 : "=f"(a.x), "=f"(a.y), "=f"(a.z), "=f"(a.w),
                   "=f"(b.x), "=f"(b.y), "=f"(b.z), "=f"(b.w)
                 : "l"(p));
}

__device__ __forceinline__ float relu4(float4 v)
{
    return fmaxf(v.x, 0.0f) + fmaxf(v.y, 0.0f)
         + fmaxf(v.z, 0.0f) + fmaxf(v.w, 0.0f);
}

__device__ __forceinline__ float block_reduce(float acc, float* warp_sums)
{
    #pragma unroll
    for (int off = 16; off > 0; off >>= 1)
        acc += __shfl_xor_sync(0xFFFFFFFFu, acc, off);

    int lane = threadIdx.x & 31;
    int wid = threadIdx.x >> 5;
    if (lane == 0) warp_sums[wid] = acc;
    __syncthreads();

    float s = 0.0f;
    if (wid == 0) {
        s = (lane < NTHREADS / 32) ? warp_sums[lane] : 0.0f;
        #pragma unroll
        for (int off = 16; off > 0; off >>= 1)
            s += __shfl_xor_sync(0xFFFFFFFFu, s, off);
    }
    return s;  // valid in warp 0 lane 0
}

__global__ void __launch_bounds__(NTHREADS, 8) kan_fused_kernel(
    const float* __restrict__ x, int n_vec8, float* __restrict__ out)
{
    int tid = blockIdx.x * blockDim.x + threadIdx.x;
    const int stride = NBLOCKS * NTHREADS;

    // Unroll x2 over 32-byte loads: two independent LDG.256 in flight.
    float a0 = 0.0f, a1 = 0.0f;
    int i = tid;
    for (; i + stride < n_vec8; i += 2 * stride) {
        float4 p0, p1, q0, q1;
        ldg256(x + (size_t)i * 8, p0, p1);
        ldg256(x + (size_t)(i + stride) * 8, q0, q1);
        a0 += relu4(p0) + relu4(p1);
        a1 += relu4(q0) + relu4(q1);
    }
    if (i < n_vec8) {
        float4 p0, p1;
        ldg256(x + (size_t)i * 8, p0, p1);
        a0 += relu4(p0) + relu4(p1);
    }

    float acc = a0 + a1;

    __shared__ float warp_sums[NTHREADS / 32];
    float bsum = block_reduce(acc, warp_sums);

    // Publish partial, elect last block.
    __shared__ bool is_last;
    if (threadIdx.x == 0) {
        g_partials[blockIdx.x] = bsum;
        __threadfence();
        unsigned int prev = atomicAdd(&g_count, 1u);
        is_last = (prev == (unsigned int)(gridDim.x - 1));
    }
    __syncthreads();

    if (is_last) {
        // 256 threads reduce NBLOCKS partials in fixed order.
        float facc = 0.0f;
        for (int k = threadIdx.x; k < NBLOCKS; k += NTHREADS)
            facc += g_partials[k];

        __syncthreads();  // warp_sums reuse
        float total = block_reduce(facc, warp_sums);

        if (threadIdx.x == 0) {
            out[0] = fmaxf(total, 0.0f);  // outer relu
            g_count = 0;                  // reset for graph replay
        }
    }
}

extern "C" void kernel_launch(void* const* d_in, const int* in_sizes, int n_in,
                              void* d_out, int out_size)
{
    const float* x = (const float*)d_in[0];
    float* out = (float*)d_out;
    int n = in_sizes[0];
    int n_vec8 = n / 8;  // N = 2^25, divisible by 8

    kan_fused_kernel<<<NBLOCKS, NTHREADS>>>(x, n_vec8, out);
}